// round 4
// baseline (speedup 1.0000x reference)
#include <cuda_runtime.h>
#include <cstdint>

#define THREADS 512
#define RANK 8
#define K4 1024            // K/4
#define N4 1024            // N/4
#define MAXROWS 64
#define RB 3               // rows per pipelined phase-1 batch
#define LORA_SCALE 2.0f    // alpha/r = 16/8

// ---- packed f32x2 helpers (FFMA2 only reachable via PTX) ----
__device__ __forceinline__ uint64_t pack2(float lo, float hi) {
    uint64_t r; asm("mov.b64 %0, {%1, %2};" : "=l"(r) : "f"(lo), "f"(hi)); return r;
}
__device__ __forceinline__ void unpack2(uint64_t v, float& lo, float& hi) {
    asm("mov.b64 {%0, %1}, %2;" : "=f"(lo), "=f"(hi) : "l"(v));
}
__device__ __forceinline__ uint64_t fma2(uint64_t a, uint64_t b, uint64_t c) {
    uint64_t d; asm("fma.rn.f32x2 %0, %1, %2, %3;" : "=l"(d) : "l"(a), "l"(b), "l"(c)); return d;
}

__global__ __launch_bounds__(THREADS, 1)
void lora_fused_kernel(const float4* __restrict__ x4,
                       const float4* __restrict__ A4,
                       const float4* __restrict__ B4,
                       float4* __restrict__ out4,
                       int rows, int grid)
{
    __shared__ float s_part[MAXROWS * 128];   // [row][warp16][j8]
    __shared__ float s_t[MAXROWS * RANK];

    const int tid  = threadIdx.x;
    const int lane = tid & 31;
    const int warp = tid >> 5;

    const int r0 = (int)((long)blockIdx.x * rows / grid);
    const int r1 = (int)((long)(blockIdx.x + 1) * rows / grid);
    const int nr = r1 - r0;                   // <= MAXROWS

    const int c0 = tid;
    const int c1 = tid + THREADS;

    // ---------------- A cache: 2 chunks x 4 k x 4 j-pairs (64 regs) ----------
    uint64_t a2[2][4][4];
#pragma unroll
    for (int ch = 0; ch < 2; ch++) {
        const int c = ch ? c1 : c0;
#pragma unroll
        for (int kk = 0; kk < 4; kk++) {
            float4 lo = A4[c * 8 + kk * 2];
            float4 hi = A4[c * 8 + kk * 2 + 1];
            a2[ch][kk][0] = pack2(lo.x, lo.y);
            a2[ch][kk][1] = pack2(lo.z, lo.w);
            a2[ch][kk][2] = pack2(hi.x, hi.y);
            a2[ch][kk][3] = pack2(hi.z, hi.w);
        }
    }

    const int j_mine = ((lane >> 4) & 1) * 4 + ((lane >> 3) & 1) * 2 + ((lane >> 2) & 1);
    const bool write_lane = (lane & 3) == 0;
    const bool h  = (lane & 16) != 0;
    const bool qb = (lane & 8) != 0;
    const bool ob = (lane & 4) != 0;

    // ---------------- Phase 1: pipelined (prefetch next batch before reduce) --
    float4 xvA[RB], xvB[RB];
#pragma unroll
    for (int r = 0; r < RB; r++) {
        int row = (r < nr) ? r : (nr - 1);
        xvA[r] = x4[(size_t)(r0 + row) * K4 + c0];
    }
#pragma unroll
    for (int r = 0; r < RB; r++) {
        int row = (r < nr) ? r : (nr - 1);
        xvB[r] = x4[(size_t)(r0 + row) * K4 + c1];
    }

    for (int rb = 0; rb < nr; rb += RB) {
        uint64_t p2[RB][4];
#pragma unroll
        for (int r = 0; r < RB; r++)
#pragma unroll
            for (int jp = 0; jp < 4; jp++) p2[r][jp] = 0ull;

        const int nb = rb + RB;
        const bool more = (nb < nr);

        // FMA chunk 0 (consumes xvA), then immediately refill xvA for batch n+1
#pragma unroll
        for (int r = 0; r < RB; r++) {
            const float xc[4] = {xvA[r].x, xvA[r].y, xvA[r].z, xvA[r].w};
#pragma unroll
            for (int kk = 0; kk < 4; kk++) {
                uint64_t xs = pack2(xc[kk], xc[kk]);
#pragma unroll
                for (int jp = 0; jp < 4; jp++)
                    p2[r][jp] = fma2(xs, a2[0][kk][jp], p2[r][jp]);
            }
        }
        if (more) {
#pragma unroll
            for (int r = 0; r < RB; r++) {
                int row = (nb + r < nr) ? (nb + r) : (nr - 1);
                xvA[r] = x4[(size_t)(r0 + row) * K4 + c0];
            }
        }

        // FMA chunk 1 (consumes xvB), refill xvB
#pragma unroll
        for (int r = 0; r < RB; r++) {
            const float xc[4] = {xvB[r].x, xvB[r].y, xvB[r].z, xvB[r].w};
#pragma unroll
            for (int kk = 0; kk < 4; kk++) {
                uint64_t xs = pack2(xc[kk], xc[kk]);
#pragma unroll
                for (int jp = 0; jp < 4; jp++)
                    p2[r][jp] = fma2(xs, a2[1][kk][jp], p2[r][jp]);
            }
        }
        if (more) {
#pragma unroll
            for (int r = 0; r < RB; r++) {
                int row = (nb + r < nr) ? (nb + r) : (nr - 1);
                xvB[r] = x4[(size_t)(r0 + row) * K4 + c1];
            }
        }

        // Folding butterfly reduce for the RB rows (next batch's loads in flight)
#pragma unroll
        for (int r = 0; r < RB; r++) {
            float p[8];
#pragma unroll
            for (int jp = 0; jp < 4; jp++) unpack2(p2[r][jp], p[2 * jp], p[2 * jp + 1]);

            float q[4];
#pragma unroll
            for (int m = 0; m < 4; m++) {
                float send = h ? p[m] : p[m + 4];
                float keep = h ? p[m + 4] : p[m];
                q[m] = keep + __shfl_xor_sync(0xffffffffu, send, 16);
            }
            float u[2];
#pragma unroll
            for (int m = 0; m < 2; m++) {
                float send = qb ? q[m] : q[m + 2];
                float keep = qb ? q[m + 2] : q[m];
                u[m] = keep + __shfl_xor_sync(0xffffffffu, send, 8);
            }
            float send = ob ? u[0] : u[1];
            float keep = ob ? u[1] : u[0];
            float w = keep + __shfl_xor_sync(0xffffffffu, send, 4);
            w += __shfl_xor_sync(0xffffffffu, w, 2);
            w += __shfl_xor_sync(0xffffffffu, w, 1);
            if (write_lane && (rb + r) < nr)
                s_part[(rb + r) * 128 + warp * 8 + j_mine] = w;
        }
    }

    // ---------------- B cache load BEFORE the sync: overlaps reduce ----------
    uint64_t b2[2][8][2];
#pragma unroll
    for (int ch = 0; ch < 2; ch++) {
        const int c = ch ? c1 : c0;
#pragma unroll
        for (int j = 0; j < RANK; j++) {
            float4 v = B4[j * N4 + c];
            v.x *= LORA_SCALE; v.y *= LORA_SCALE; v.z *= LORA_SCALE; v.w *= LORA_SCALE;
            b2[ch][j][0] = pack2(v.x, v.y);
            b2[ch][j][1] = pack2(v.z, v.w);
        }
    }

    __syncthreads();

    // ---------------- Cross-warp reduce into s_t ------------------------------
    for (int i = tid; i < nr * RANK; i += THREADS) {
        const int row = i >> 3, j = i & 7;
        float s = 0.0f;
#pragma unroll
        for (int w = 0; w < 16; w++) s += s_part[row * 128 + w * 8 + j];
        s_t[i] = s;
    }
    __syncthreads();

    // ---------------- Phase 2: out = t @ (B*scale), 2 rows/iter ---------------
    for (int rb = 0; rb < nr; rb += 2) {
        const int rA = rb;
        const int rB = (rb + 1 < nr) ? rb + 1 : rb;   // clamp (dup store harmless)

        float4 tA0 = *reinterpret_cast<const float4*>(&s_t[rA * RANK]);
        float4 tA1 = *reinterpret_cast<const float4*>(&s_t[rA * RANK + 4]);
        float4 tB0 = *reinterpret_cast<const float4*>(&s_t[rB * RANK]);
        float4 tB1 = *reinterpret_cast<const float4*>(&s_t[rB * RANK + 4]);

        uint64_t tsA[8], tsB[8];
        tsA[0] = pack2(tA0.x, tA0.x); tsA[1] = pack2(tA0.y, tA0.y);
        tsA[2] = pack2(tA0.z, tA0.z); tsA[3] = pack2(tA0.w, tA0.w);
        tsA[4] = pack2(tA1.x, tA1.x); tsA[5] = pack2(tA1.y, tA1.y);
        tsA[6] = pack2(tA1.z, tA1.z); tsA[7] = pack2(tA1.w, tA1.w);
        tsB[0] = pack2(tB0.x, tB0.x); tsB[1] = pack2(tB0.y, tB0.y);
        tsB[2] = pack2(tB0.z, tB0.z); tsB[3] = pack2(tB0.w, tB0.w);
        tsB[4] = pack2(tB1.x, tB1.x); tsB[5] = pack2(tB1.y, tB1.y);
        tsB[6] = pack2(tB1.z, tB1.z); tsB[7] = pack2(tB1.w, tB1.w);

        const size_t obA = (size_t)(r0 + rA) * N4;
        const size_t obB = (size_t)(r0 + rB) * N4;
#pragma unroll
        for (int ch = 0; ch < 2; ch++) {
            const int c = ch ? c1 : c0;
            uint64_t oA0 = 0ull, oA1 = 0ull, oB0 = 0ull, oB1 = 0ull;
#pragma unroll
            for (int j = 0; j < RANK; j++) {
                oA0 = fma2(tsA[j], b2[ch][j][0], oA0);
                oA1 = fma2(tsA[j], b2[ch][j][1], oA1);
                oB0 = fma2(tsB[j], b2[ch][j][0], oB0);
                oB1 = fma2(tsB[j], b2[ch][j][1], oB1);
            }
            float4 oA, oB;
            unpack2(oA0, oA.x, oA.y); unpack2(oA1, oA.z, oA.w);
            unpack2(oB0, oB.x, oB.y); unpack2(oB1, oB.z, oB.w);
            out4[obA + c] = oA;
            out4[obB + c] = oB;
        }
    }
}

extern "C" void kernel_launch(void* const* d_in, const int* in_sizes, int n_in,
                              void* d_out, int out_size)
{
    const float4* x4 = (const float4*)d_in[0];
    const float4* A4 = (const float4*)d_in[1];
    const float4* B4 = (const float4*)d_in[2];
    float4* out4 = (float4*)d_out;

    const int K    = in_sizes[1] / RANK;
    const int rows = in_sizes[0] / K;

    int sms = 148;
    cudaDeviceGetAttribute(&sms, cudaDevAttrMultiProcessorCount, 0);

    lora_fused_kernel<<<sms, THREADS>>>(x4, A4, B4, out4, rows, sms);
}